// round 1
// baseline (speedup 1.0000x reference)
#include <cuda_runtime.h>
#include <cuda_bf16.h>
#include <math.h>

// Problem constants
#define Bv 4
#define Lv 2048
#define Dv 1024
#define Hv 16
#define HDv 64
#define Mv (Bv * Lv)          // 8192 rows
#define EPSv 1e-5f

// ---------------- scratch (device globals; no allocs allowed) ----------------
__device__ float g_Q[Bv * Hv * Lv * HDv];  // [B,H,L,HD]
__device__ float g_K[Bv * Hv * Lv * HDv];
__device__ float g_V[Bv * Hv * Lv * HDv];
__device__ float g_O[Mv * Dv];             // attention out, [B,L,D]
__device__ float g_Y[Mv * Dv];             // pre-LN residual sum

// ---------------- SGEMM: C[M,N] = A[M,K] * W[K,N] + bias (+residual) ----------------
// M=8192, N=1024, K=1024. BM=BN=128, BK=8, 256 threads, 8x8 per-thread tile.
// out_mode 0: row-major [M,N]; out_mode 1: head-split [B,H,L,HD].
#define OUT_Q 0
#define OUT_K 1
#define OUT_V 2
#define OUT_Y 3

__global__ __launch_bounds__(256, 2)
void sgemm_kernel(const float* __restrict__ A_ext, int a_sel,
                  const float* __restrict__ W,
                  const float* __restrict__ bias,
                  const float* __restrict__ residual,
                  int out_sel, int out_mode)
{
    __shared__ float As[8][128];
    __shared__ float Bs[8][128];

    const float* A = a_sel ? g_O : A_ext;
    float* outp;
    switch (out_sel) {
        case OUT_Q: outp = g_Q; break;
        case OUT_K: outp = g_K; break;
        case OUT_V: outp = g_V; break;
        default:    outp = g_Y; break;
    }

    const int tid  = threadIdx.x;
    const int brow = blockIdx.y;   // M tile index
    const int bcol = blockIdx.x;   // N tile index

    const float* Ab = A + (size_t)brow * 128 * Dv;
    const float* Wb = W + bcol * 128;

    const int a_row  = tid >> 1;          // 0..127
    const int a_col4 = (tid & 1) * 4;     // 0 or 4
    const int b_row  = tid >> 5;          // 0..7
    const int b_col  = (tid & 31) * 4;    // 0..124

    const int ty = tid >> 4;              // 0..15
    const int tx = tid & 15;              // 0..15

    float acc[8][8];
#pragma unroll
    for (int i = 0; i < 8; i++)
#pragma unroll
        for (int j = 0; j < 8; j++) acc[i][j] = 0.f;

    for (int k0 = 0; k0 < Dv; k0 += 8) {
        float4 av = *(const float4*)(Ab + a_row * Dv + k0 + a_col4);
        As[a_col4 + 0][a_row] = av.x;
        As[a_col4 + 1][a_row] = av.y;
        As[a_col4 + 2][a_row] = av.z;
        As[a_col4 + 3][a_row] = av.w;
        float4 wv = *(const float4*)(Wb + (size_t)(k0 + b_row) * Dv + b_col);
        *(float4*)&Bs[b_row][b_col] = wv;
        __syncthreads();

#pragma unroll
        for (int k = 0; k < 8; k++) {
            float4 a0 = *(float4*)&As[k][ty * 8];
            float4 a1 = *(float4*)&As[k][ty * 8 + 4];
            float4 b0 = *(float4*)&Bs[k][tx * 8];
            float4 b1 = *(float4*)&Bs[k][tx * 8 + 4];
            float ar[8] = {a0.x, a0.y, a0.z, a0.w, a1.x, a1.y, a1.z, a1.w};
            float br[8] = {b0.x, b0.y, b0.z, b0.w, b1.x, b1.y, b1.z, b1.w};
#pragma unroll
            for (int i = 0; i < 8; i++)
#pragma unroll
                for (int j = 0; j < 8; j++) acc[i][j] += ar[i] * br[j];
        }
        __syncthreads();
    }

    // epilogue
    const int m0 = brow * 128 + ty * 8;
    const int n0 = bcol * 128 + tx * 8;
#pragma unroll
    for (int i = 0; i < 8; i++) {
        const int m = m0 + i;
#pragma unroll
        for (int j = 0; j < 8; j++) {
            const int n = n0 + j;
            float v = acc[i][j] + bias[n];
            if (residual) v += residual[(size_t)m * Dv + n];
            if (out_mode == 0) {
                outp[(size_t)m * Dv + n] = v;
            } else {
                const int b = m >> 11, l = m & 2047;
                const int h = n >> 6,  hd = n & 63;
                outp[((((size_t)b * Hv + h) * Lv) + l) * HDv + hd] = v;
            }
        }
    }
}

// ---------------- Flash attention, fp32, Br=Bc=64, HD=64 ----------------
// Grid: x = L/64 = 32 (q tile), y = B*H = 64. Block = 256 threads.
// smem: Qs,Ks,Vs,Ps each [64][68] floats = 69632 bytes (dynamic).
#define FLASH_SMEM (4 * 64 * 68 * 4)

__global__ __launch_bounds__(256, 1)
void flash_kernel()
{
    extern __shared__ float sm[];
    float (*Qs)[68] = (float(*)[68])(sm);
    float (*Ks)[68] = (float(*)[68])(sm + 64 * 68);
    float (*Vs)[68] = (float(*)[68])(sm + 2 * 64 * 68);
    float (*Ps)[68] = (float(*)[68])(sm + 3 * 64 * 68);

    const int tid = threadIdx.x;
    const int bh  = blockIdx.y;               // b*16 + h
    const int qb  = blockIdx.x;
    const int ty  = tid >> 4;                 // 0..15 (row group)
    const int tx  = tid & 15;                 // 0..15 (col group)

    const float* Qp = g_Q + ((size_t)bh * Lv + qb * 64) * HDv;
    const float* Kp = g_K + (size_t)bh * Lv * HDv;
    const float* Vp = g_V + (size_t)bh * Lv * HDv;

    // Load Q tile (pre-scaled by 1/sqrt(HD) = 0.125)
    {
        const int r = tid >> 2;
        const int c0 = (tid & 3) * 16;
#pragma unroll
        for (int u = 0; u < 4; u++) {
            float4 qv = *(const float4*)(Qp + r * HDv + c0 + u * 4);
            qv.x *= 0.125f; qv.y *= 0.125f; qv.z *= 0.125f; qv.w *= 0.125f;
            *(float4*)&Qs[r][c0 + u * 4] = qv;
        }
    }

    float m_i[4], l_i[4], acc[4][4];
#pragma unroll
    for (int i = 0; i < 4; i++) {
        m_i[i] = -1e30f; l_i[i] = 0.f;
#pragma unroll
        for (int j = 0; j < 4; j++) acc[i][j] = 0.f;
    }

    const int r4 = ty * 4;
    const int c4 = tx * 4;

    for (int kb = 0; kb < Lv / 64; kb++) {
        // load K,V tiles
        {
            const int r = tid >> 2;
            const int c0 = (tid & 3) * 16;
            const float* kg = Kp + (kb * 64 + r) * HDv;
            const float* vg = Vp + (kb * 64 + r) * HDv;
#pragma unroll
            for (int u = 0; u < 4; u++) {
                *(float4*)&Ks[r][c0 + u * 4] = *(const float4*)(kg + c0 + u * 4);
                *(float4*)&Vs[r][c0 + u * 4] = *(const float4*)(vg + c0 + u * 4);
            }
        }
        __syncthreads();

        // S = Q K^T (scaled), 4x4 per thread
        float s[4][4];
#pragma unroll
        for (int i = 0; i < 4; i++)
#pragma unroll
            for (int j = 0; j < 4; j++) s[i][j] = 0.f;

#pragma unroll 8
        for (int d = 0; d < 64; d += 4) {
            float4 a[4], b[4];
#pragma unroll
            for (int i = 0; i < 4; i++) a[i] = *(float4*)&Qs[r4 + i][d];
#pragma unroll
            for (int j = 0; j < 4; j++) b[j] = *(float4*)&Ks[c4 + j][d];
#pragma unroll
            for (int i = 0; i < 4; i++)
#pragma unroll
                for (int j = 0; j < 4; j++)
                    s[i][j] += a[i].x * b[j].x + a[i].y * b[j].y +
                               a[i].z * b[j].z + a[i].w * b[j].w;
        }

        // online softmax per row (16 lanes per row == one half-warp)
#pragma unroll
        for (int i = 0; i < 4; i++) {
            float vm = fmaxf(fmaxf(s[i][0], s[i][1]), fmaxf(s[i][2], s[i][3]));
#pragma unroll
            for (int off = 8; off > 0; off >>= 1)
                vm = fmaxf(vm, __shfl_xor_sync(0xffffffffu, vm, off));
            const float mnew = fmaxf(m_i[i], vm);
            const float corr = __expf(m_i[i] - mnew);
            float rs = 0.f;
#pragma unroll
            for (int j = 0; j < 4; j++) {
                const float p = __expf(s[i][j] - mnew);
                s[i][j] = p;
                rs += p;
            }
#pragma unroll
            for (int off = 8; off > 0; off >>= 1)
                rs += __shfl_xor_sync(0xffffffffu, rs, off);
            l_i[i] = l_i[i] * corr + rs;
            m_i[i] = mnew;
#pragma unroll
            for (int j = 0; j < 4; j++) acc[i][j] *= corr;
#pragma unroll
            for (int j = 0; j < 4; j++) Ps[r4 + i][c4 + j] = s[i][j];
        }
        __syncwarp();

        // O += P V  (thread owns rows r4..r4+3, cols c4..c4+3)
#pragma unroll 4
        for (int c = 0; c < 64; c += 4) {
            float4 p[4], v[4];
#pragma unroll
            for (int i = 0; i < 4; i++) p[i] = *(float4*)&Ps[r4 + i][c];
#pragma unroll
            for (int cc = 0; cc < 4; cc++) v[cc] = *(float4*)&Vs[c + cc][c4];
#pragma unroll
            for (int i = 0; i < 4; i++) {
                acc[i][0] += p[i].x * v[0].x + p[i].y * v[1].x + p[i].z * v[2].x + p[i].w * v[3].x;
                acc[i][1] += p[i].x * v[0].y + p[i].y * v[1].y + p[i].z * v[2].y + p[i].w * v[3].y;
                acc[i][2] += p[i].x * v[0].z + p[i].y * v[1].z + p[i].z * v[2].z + p[i].w * v[3].z;
                acc[i][3] += p[i].x * v[0].w + p[i].y * v[1].w + p[i].z * v[2].w + p[i].w * v[3].w;
            }
        }
        __syncthreads();
    }

    // final normalize and write to g_O in [B,L,D]
    const int b = bh >> 4, h = bh & 15;
#pragma unroll
    for (int i = 0; i < 4; i++) {
        const float inv = 1.f / l_i[i];
        const int l = qb * 64 + r4 + i;
        float4 o;
        o.x = acc[i][0] * inv; o.y = acc[i][1] * inv;
        o.z = acc[i][2] * inv; o.w = acc[i][3] * inv;
        *(float4*)&g_O[((size_t)b * Lv + l) * Dv + h * HDv + c4] = o;
    }
}

// ---------------- LayerNorm: one block per row ----------------
__device__ __forceinline__ float blockReduceSum(float val)
{
    __shared__ float sh[8];
    const int lane = threadIdx.x & 31;
    const int wid  = threadIdx.x >> 5;
#pragma unroll
    for (int o = 16; o > 0; o >>= 1) val += __shfl_xor_sync(0xffffffffu, val, o);
    __syncthreads();
    if (lane == 0) sh[wid] = val;
    __syncthreads();
    if (wid == 0) {
        val = (lane < 8) ? sh[lane] : 0.f;
#pragma unroll
        for (int o = 4; o > 0; o >>= 1) val += __shfl_xor_sync(0xffffffffu, val, o);
        if (lane == 0) sh[0] = val;
    }
    __syncthreads();
    return sh[0];
}

__global__ __launch_bounds__(256)
void layernorm_kernel(const float* __restrict__ gamma,
                      const float* __restrict__ beta,
                      float* __restrict__ out)
{
    const int row = blockIdx.x;
    const int tid = threadIdx.x;
    const float* y = g_Y + (size_t)row * Dv;

    float v[4];
#pragma unroll
    for (int i = 0; i < 4; i++) v[i] = y[tid + i * 256];

    const float total = blockReduceSum(v[0] + v[1] + v[2] + v[3]);
    const float mu = total * (1.f / Dv);

    float d2 = 0.f;
#pragma unroll
    for (int i = 0; i < 4; i++) {
        const float d = v[i] - mu;
        d2 += d * d;
    }
    const float var = blockReduceSum(d2) * (1.f / Dv);
    const float rs = rsqrtf(var + EPSv);

#pragma unroll
    for (int i = 0; i < 4; i++) {
        const int c = tid + i * 256;
        out[(size_t)row * Dv + c] = (v[i] - mu) * rs * gamma[c] + beta[c];
    }
}

// ---------------- launch ----------------
extern "C" void kernel_launch(void* const* d_in, const int* in_sizes, int n_in,
                              void* d_out, int out_size)
{
    (void)in_sizes; (void)n_in; (void)out_size;
    const float* x     = (const float*)d_in[0];
    const float* Wq    = (const float*)d_in[1];
    const float* bq    = (const float*)d_in[2];
    const float* Wk    = (const float*)d_in[3];
    const float* bk    = (const float*)d_in[4];
    const float* Wv    = (const float*)d_in[5];
    const float* bv    = (const float*)d_in[6];
    const float* Wo    = (const float*)d_in[7];
    const float* bo    = (const float*)d_in[8];
    const float* gamma = (const float*)d_in[9];
    const float* beta  = (const float*)d_in[10];
    float* out = (float*)d_out;

    cudaFuncSetAttribute(flash_kernel,
                         cudaFuncAttributeMaxDynamicSharedMemorySize, FLASH_SMEM);

    dim3 gg(Dv / 128, Mv / 128);   // (8, 64)
    sgemm_kernel<<<gg, 256>>>(x, 0, Wq, bq, nullptr, OUT_Q, 1);
    sgemm_kernel<<<gg, 256>>>(x, 0, Wk, bk, nullptr, OUT_K, 1);
    sgemm_kernel<<<gg, 256>>>(x, 0, Wv, bv, nullptr, OUT_V, 1);

    flash_kernel<<<dim3(Lv / 64, Bv * Hv), 256, FLASH_SMEM>>>();

    sgemm_kernel<<<gg, 256>>>(nullptr, 1, Wo, bo, x, OUT_Y, 0);

    layernorm_kernel<<<Mv, 256>>>(gamma, beta, out);
}

// round 3
// speedup vs baseline: 1.8221x; 1.8221x over previous
#include <cuda_runtime.h>
#include <cuda_bf16.h>
#include <math.h>

// Problem constants
#define Bv 4
#define Lv 2048
#define Dv 1024
#define Hv 16
#define HDv 64
#define Mv (Bv * Lv)          // 8192 rows
#define EPSv 1e-5f

// ---------------- scratch (device globals; no allocs allowed) ----------------
__device__ float g_Q[Bv * Hv * Lv * HDv];  // [B,H,L,HD]
__device__ float g_K[Bv * Hv * Lv * HDv];
__device__ float g_V[Bv * Hv * Lv * HDv];
__device__ float g_O[Mv * Dv];             // attention out, [B,L,D]
__device__ float g_Y[Mv * Dv];             // pre-LN residual sum

#define OUT_Q 0
#define OUT_K 1
#define OUT_V 2
#define OUT_Y 3

// ---------------- tf32 helpers ----------------
__device__ __forceinline__ unsigned f2tf32(float x) {
    unsigned r;
    asm volatile("cvt.rna.tf32.f32 %0, %1;" : "=r"(r) : "f"(x));
    return r;
}

__device__ __forceinline__ void mma16818(float* c, const unsigned* a, const unsigned* b) {
    asm volatile(
        "mma.sync.aligned.m16n8k8.row.col.f32.tf32.tf32.f32 "
        "{%0,%1,%2,%3}, {%4,%5,%6,%7}, {%8,%9}, {%0,%1,%2,%3};"
        : "+f"(c[0]), "+f"(c[1]), "+f"(c[2]), "+f"(c[3])
        : "r"(a[0]), "r"(a[1]), "r"(a[2]), "r"(a[3]), "r"(b[0]), "r"(b[1]));
}

// ---------------- tf32 tensor-core GEMM ----------------
// C[M=8192, N=1024] = A[M,K=1024] * W[K,N] + bias (+residual)
// Block 128x128, BK=16, 256 threads = 8 warps (2 x 4), warp tile 64x32.
// smem stride 136 (136 mod 32 == 8 -> conflict-free fragment loads).
#define SSTR 136

__global__ __launch_bounds__(256, 2)
void gemm_tc_kernel(const float* __restrict__ A_ext, int a_sel,
                    const float* __restrict__ W,
                    const float* __restrict__ bias,
                    const float* __restrict__ residual,
                    int out_sel, int out_mode)
{
    __shared__ unsigned As[16 * SSTR];
    __shared__ unsigned Bs[16 * SSTR];

    const float* A = a_sel ? g_O : A_ext;
    float* outp;
    switch (out_sel) {
        case OUT_Q: outp = g_Q; break;
        case OUT_K: outp = g_K; break;
        case OUT_V: outp = g_V; break;
        default:    outp = g_Y; break;
    }

    const int tid  = threadIdx.x;
    const int brow = blockIdx.y;   // M tile
    const int bcol = blockIdx.x;   // N tile
    const int wid  = tid >> 5;
    const int lane = tid & 31;
    const int wm   = wid & 1;      // 0..1  (M dir, 64 rows each)
    const int wn   = wid >> 1;     // 0..3  (N dir, 32 cols each)
    const int row4 = lane >> 2;    // 0..7  (groupID)
    const int col  = lane & 3;     // 0..3  (threadID in group)

    // global load mapping
    const int la_m  = tid >> 1;            // 0..127
    const int la_k  = (tid & 1) * 8;       // 0 or 8
    const int lb_k  = tid >> 4;            // 0..15
    const int lb_n  = (tid & 15) * 8;      // 0..120

    const float* Ab = A + (size_t)(brow * 128 + la_m) * Dv + la_k;
    const float* Wb = W + (size_t)lb_k * Dv + bcol * 128 + lb_n;

    float acc[4][4][4];
#pragma unroll
    for (int i = 0; i < 4; i++)
#pragma unroll
        for (int j = 0; j < 4; j++)
#pragma unroll
            for (int r = 0; r < 4; r++) acc[i][j][r] = 0.f;

    for (int k0 = 0; k0 < Dv; k0 += 16) {
        // A: 8 floats per thread, transpose into As[k][m]
        float4 av0 = *(const float4*)(Ab + k0);
        float4 av1 = *(const float4*)(Ab + k0 + 4);
        As[(la_k + 0) * SSTR + la_m] = f2tf32(av0.x);
        As[(la_k + 1) * SSTR + la_m] = f2tf32(av0.y);
        As[(la_k + 2) * SSTR + la_m] = f2tf32(av0.z);
        As[(la_k + 3) * SSTR + la_m] = f2tf32(av0.w);
        As[(la_k + 4) * SSTR + la_m] = f2tf32(av1.x);
        As[(la_k + 5) * SSTR + la_m] = f2tf32(av1.y);
        As[(la_k + 6) * SSTR + la_m] = f2tf32(av1.z);
        As[(la_k + 7) * SSTR + la_m] = f2tf32(av1.w);
        // B: 8 floats per thread, direct into Bs[k][n]
        float4 bv0 = *(const float4*)(Wb + (size_t)k0 * Dv);
        float4 bv1 = *(const float4*)(Wb + (size_t)k0 * Dv + 4);
        Bs[lb_k * SSTR + lb_n + 0] = f2tf32(bv0.x);
        Bs[lb_k * SSTR + lb_n + 1] = f2tf32(bv0.y);
        Bs[lb_k * SSTR + lb_n + 2] = f2tf32(bv0.z);
        Bs[lb_k * SSTR + lb_n + 3] = f2tf32(bv0.w);
        Bs[lb_k * SSTR + lb_n + 4] = f2tf32(bv1.x);
        Bs[lb_k * SSTR + lb_n + 5] = f2tf32(bv1.y);
        Bs[lb_k * SSTR + lb_n + 6] = f2tf32(bv1.z);
        Bs[lb_k * SSTR + lb_n + 7] = f2tf32(bv1.w);
        __syncthreads();

#pragma unroll
        for (int ks = 0; ks < 16; ks += 8) {
            unsigned af[4][4], bf[4][2];
#pragma unroll
            for (int i = 0; i < 4; i++) {
                const int mb = wm * 64 + i * 16 + row4;
                af[i][0] = As[(ks + col) * SSTR + mb];
                af[i][1] = As[(ks + col) * SSTR + mb + 8];
                af[i][2] = As[(ks + col + 4) * SSTR + mb];
                af[i][3] = As[(ks + col + 4) * SSTR + mb + 8];
            }
#pragma unroll
            for (int j = 0; j < 4; j++) {
                const int nb = wn * 32 + j * 8 + row4;
                bf[j][0] = Bs[(ks + col) * SSTR + nb];
                bf[j][1] = Bs[(ks + col + 4) * SSTR + nb];
            }
#pragma unroll
            for (int i = 0; i < 4; i++)
#pragma unroll
                for (int j = 0; j < 4; j++)
                    mma16818(acc[i][j], af[i], bf[j]);
        }
        __syncthreads();
    }

    // epilogue: c0=(r,2c), c1=(r,2c+1), c2=(r+8,2c), c3=(r+8,2c+1)
#pragma unroll
    for (int i = 0; i < 4; i++) {
#pragma unroll
        for (int j = 0; j < 4; j++) {
            const int m_lo = brow * 128 + wm * 64 + i * 16 + row4;
            const int n0   = bcol * 128 + wn * 32 + j * 8 + col * 2;
#pragma unroll
            for (int half = 0; half < 2; half++) {
                const int m = m_lo + half * 8;
                float v0 = acc[i][j][half * 2 + 0] + bias[n0];
                float v1 = acc[i][j][half * 2 + 1] + bias[n0 + 1];
                if (residual) {
                    v0 += residual[(size_t)m * Dv + n0];
                    v1 += residual[(size_t)m * Dv + n0 + 1];
                }
                if (out_mode == 0) {
                    *(float2*)&outp[(size_t)m * Dv + n0] = make_float2(v0, v1);
                } else {
                    const int b = m >> 11, l = m & 2047;
                    const int h = n0 >> 6, hd = n0 & 63;
                    float* p = &outp[((((size_t)b * Hv + h) * Lv) + l) * HDv + hd];
                    p[0] = v0; p[1] = v1;
                }
            }
        }
    }
}

// ---------------- Flash attention, fp32, Br=Bc=64, HD=64 ----------------
// Q and K stored TRANSPOSED in smem (Qt[d][q], Kt[d][k], stride 68):
// QK^T inner loop reads are broadcast (Qt) and stride-4 (Kt) float4s ->
// conflict-free and 16B-aligned. V, P row-major stride 68 (conflict-free).
#define FS 68
#define FLASH_SMEM (4 * 64 * FS * 4)

__global__ __launch_bounds__(256, 1)
void flash_kernel()
{
    extern __shared__ float sm[];
    float* Qt = sm;                 // [64 d][FS] -> Qt[d*FS + q]
    float* Kt = sm + 64 * FS;       // [64 d][FS] -> Kt[d*FS + k]
    float* Vs = sm + 2 * 64 * FS;   // [64 k][FS] -> Vs[k*FS + hd]
    float* Ps = sm + 3 * 64 * FS;   // [64 q][FS] -> Ps[q*FS + k]

    const int tid = threadIdx.x;
    const int bh  = blockIdx.y;               // b*16 + h
    const int qb  = blockIdx.x;
    const int ty  = tid >> 4;                 // 0..15 (q row group)
    const int tx  = tid & 15;                 // 0..15 (col group)

    const float* Qp = g_Q + ((size_t)bh * Lv + qb * 64) * HDv;
    const float* Kp = g_K + (size_t)bh * Lv * HDv;
    const float* Vp = g_V + (size_t)bh * Lv * HDv;

    // transpose-load mapping: r = row (q/k index), cbase + u*16 = hd column
    const int r     = tid >> 2;               // 0..63
    const int cbase = (tid & 3) * 4;          // 0,4,8,12

    // Load Q transposed, pre-scaled by 1/sqrt(HD) = 0.125
#pragma unroll
    for (int u = 0; u < 4; u++) {
        const int c = cbase + u * 16;
        float4 qv = *(const float4*)(Qp + r * HDv + c);
        Qt[(c + 0) * FS + r] = qv.x * 0.125f;
        Qt[(c + 1) * FS + r] = qv.y * 0.125f;
        Qt[(c + 2) * FS + r] = qv.z * 0.125f;
        Qt[(c + 3) * FS + r] = qv.w * 0.125f;
    }

    float m_i[4], l_i[4], acc[4][4];
#pragma unroll
    for (int i = 0; i < 4; i++) {
        m_i[i] = -1e30f; l_i[i] = 0.f;
#pragma unroll
        for (int j = 0; j < 4; j++) acc[i][j] = 0.f;
    }

    const int r4 = ty * 4;
    const int c4 = tx * 4;

    for (int kb = 0; kb < Lv / 64; kb++) {
        // load K transposed + V row-major
        {
            const float* kg = Kp + (kb * 64 + r) * HDv;
            const float* vg = Vp + (kb * 64 + r) * HDv;
#pragma unroll
            for (int u = 0; u < 4; u++) {
                const int c = cbase + u * 16;
                float4 kv = *(const float4*)(kg + c);
                Kt[(c + 0) * FS + r] = kv.x;
                Kt[(c + 1) * FS + r] = kv.y;
                Kt[(c + 2) * FS + r] = kv.z;
                Kt[(c + 3) * FS + r] = kv.w;
                *(float4*)&Vs[r * FS + c] = *(const float4*)(vg + c);
            }
        }
        __syncthreads();

        // S = Q K^T : s[i][j] = sum_d Qt[d][r4+i] * Kt[d][c4+j]
        float s[4][4];
#pragma unroll
        for (int i = 0; i < 4; i++)
#pragma unroll
            for (int j = 0; j < 4; j++) s[i][j] = 0.f;

#pragma unroll 4
        for (int d = 0; d < 64; d++) {
            float4 a = *(float4*)&Qt[d * FS + r4];   // broadcast in half-warp
            float4 b = *(float4*)&Kt[d * FS + c4];   // stride-4, conflict-free
            s[0][0] += a.x * b.x; s[0][1] += a.x * b.y; s[0][2] += a.x * b.z; s[0][3] += a.x * b.w;
            s[1][0] += a.y * b.x; s[1][1] += a.y * b.y; s[1][2] += a.y * b.z; s[1][3] += a.y * b.w;
            s[2][0] += a.z * b.x; s[2][1] += a.z * b.y; s[2][2] += a.z * b.z; s[2][3] += a.z * b.w;
            s[3][0] += a.w * b.x; s[3][1] += a.w * b.y; s[3][2] += a.w * b.z; s[3][3] += a.w * b.w;
        }

        // online softmax per row (16 lanes per row == one half-warp)
#pragma unroll
        for (int i = 0; i < 4; i++) {
            float vm = fmaxf(fmaxf(s[i][0], s[i][1]), fmaxf(s[i][2], s[i][3]));
#pragma unroll
            for (int off = 8; off > 0; off >>= 1)
                vm = fmaxf(vm, __shfl_xor_sync(0xffffffffu, vm, off));
            const float mnew = fmaxf(m_i[i], vm);
            const float corr = __expf(m_i[i] - mnew);
            float rs = 0.f;
#pragma unroll
            for (int j = 0; j < 4; j++) {
                const float p = __expf(s[i][j] - mnew);
                s[i][j] = p;
                rs += p;
            }
#pragma unroll
            for (int off = 8; off > 0; off >>= 1)
                rs += __shfl_xor_sync(0xffffffffu, rs, off);
            l_i[i] = l_i[i] * corr + rs;
            m_i[i] = mnew;
#pragma unroll
            for (int j = 0; j < 4; j++) acc[i][j] *= corr;
#pragma unroll
            for (int j = 0; j < 4; j++) Ps[(r4 + i) * FS + c4 + j] = s[i][j];
        }
        __syncwarp();

        // O += P V  (thread owns rows r4..r4+3, cols c4..c4+3 of O)
#pragma unroll 4
        for (int c = 0; c < 64; c += 4) {
            float4 p[4], v[4];
#pragma unroll
            for (int i = 0; i < 4; i++) p[i] = *(float4*)&Ps[(r4 + i) * FS + c];
#pragma unroll
            for (int cc = 0; cc < 4; cc++) v[cc] = *(float4*)&Vs[(c + cc) * FS + c4];
#pragma unroll
            for (int i = 0; i < 4; i++) {
                acc[i][0] += p[i].x * v[0].x + p[i].y * v[1].x + p[i].z * v[2].x + p[i].w * v[3].x;
                acc[i][1] += p[i].x * v[0].y + p[i].y * v[1].y + p[i].z * v[2].y + p[i].w * v[3].y;
                acc[i][2] += p[i].x * v[0].z + p[i].y * v[1].z + p[i].z * v[2].z + p[i].w * v[3].z;
                acc[i][3] += p[i].x * v[0].w + p[i].y * v[1].w + p[i].z * v[2].w + p[i].w * v[3].w;
            }
        }
        __syncthreads();
    }

    // final normalize and write to g_O in [B,L,D]
    const int b = bh >> 4, h = bh & 15;
#pragma unroll
    for (int i = 0; i < 4; i++) {
        const float inv = 1.f / l_i[i];
        const int l = qb * 64 + r4 + i;
        float4 o;
        o.x = acc[i][0] * inv; o.y = acc[i][1] * inv;
        o.z = acc[i][2] * inv; o.w = acc[i][3] * inv;
        *(float4*)&g_O[((size_t)b * Lv + l) * Dv + h * HDv + c4] = o;
    }
}

// ---------------- LayerNorm: one block per row ----------------
__device__ __forceinline__ float blockReduceSum(float val)
{
    __shared__ float sh[8];
    const int lane = threadIdx.x & 31;
    const int wid  = threadIdx.x >> 5;
#pragma unroll
    for (int o = 16; o > 0; o >>= 1) val += __shfl_xor_sync(0xffffffffu, val, o);
    __syncthreads();
    if (lane == 0) sh[wid] = val;
    __syncthreads();
    if (wid == 0) {
        val = (lane < 8) ? sh[lane] : 0.f;
#pragma unroll
        for (int o = 4; o > 0; o >>= 1) val += __shfl_xor_sync(0xffffffffu, val, o);
        if (lane == 0) sh[0] = val;
    }
    __syncthreads();
    return sh[0];
}

__global__ __launch_bounds__(256)
void layernorm_kernel(const float* __restrict__ gamma,
                      const float* __restrict__ beta,
                      float* __restrict__ out)
{
    const int row = blockIdx.x;
    const int tid = threadIdx.x;
    const float* y = g_Y + (size_t)row * Dv;

    float v[4];
#pragma unroll
    for (int i = 0; i < 4; i++) v[i] = y[tid + i * 256];

    const float total = blockReduceSum(v[0] + v[1] + v[2] + v[3]);
    const float mu = total * (1.f / Dv);

    float d2 = 0.f;
#pragma unroll
    for (int i = 0; i < 4; i++) {
        const float d = v[i] - mu;
        d2 += d * d;
    }
    const float var = blockReduceSum(d2) * (1.f / Dv);
    const float rs = rsqrtf(var + EPSv);

#pragma unroll
    for (int i = 0; i < 4; i++) {
        const int c = tid + i * 256;
        out[(size_t)row * Dv + c] = (v[i] - mu) * rs * gamma[c] + beta[c];
    }
}

// ---------------- launch ----------------
extern "C" void kernel_launch(void* const* d_in, const int* in_sizes, int n_in,
                              void* d_out, int out_size)
{
    (void)in_sizes; (void)n_in; (void)out_size;
    const float* x     = (const float*)d_in[0];
    const float* Wq    = (const float*)d_in[1];
    const float* bq    = (const float*)d_in[2];
    const float* Wk    = (const float*)d_in[3];
    const float* bk    = (const float*)d_in[4];
    const float* Wv    = (const float*)d_in[5];
    const float* bv    = (const float*)d_in[6];
    const float* Wo    = (const float*)d_in[7];
    const float* bo    = (const float*)d_in[8];
    const float* gamma = (const float*)d_in[9];
    const float* beta  = (const float*)d_in[10];
    float* out = (float*)d_out;

    cudaFuncSetAttribute(flash_kernel,
                         cudaFuncAttributeMaxDynamicSharedMemorySize, FLASH_SMEM);

    dim3 gg(Dv / 128, Mv / 128);   // (8, 64)
    gemm_tc_kernel<<<gg, 256>>>(x, 0, Wq, bq, nullptr, OUT_Q, 1);
    gemm_tc_kernel<<<gg, 256>>>(x, 0, Wk, bk, nullptr, OUT_K, 1);
    gemm_tc_kernel<<<gg, 256>>>(x, 0, Wv, bv, nullptr, OUT_V, 1);

    flash_kernel<<<dim3(Lv / 64, Bv * Hv), 256, FLASH_SMEM>>>();

    gemm_tc_kernel<<<gg, 256>>>(nullptr, 1, Wo, bo, x, OUT_Y, 0);

    layernorm_kernel<<<Mv, 256>>>(gamma, beta, out);
}

// round 4
// speedup vs baseline: 3.8559x; 2.1162x over previous
#include <cuda_runtime.h>
#include <cuda_bf16.h>
#include <math.h>

// Problem constants
#define Bv 4
#define Lv 2048
#define Dv 1024
#define Hv 16
#define HDv 64
#define Mv (Bv * Lv)          // 8192 rows
#define EPSv 1e-5f

// ---------------- scratch (device globals; no allocs allowed) ----------------
__device__ float g_Q[Bv * Hv * Lv * HDv];  // [B,H,L,HD]
__device__ float g_K[Bv * Hv * Lv * HDv];
__device__ float g_V[Bv * Hv * Lv * HDv];
__device__ float g_O[Mv * Dv];             // attention out, [B,L,D]
__device__ float g_Y[Mv * Dv];             // pre-LN residual sum

#define OUT_Q 0
#define OUT_K 1
#define OUT_V 2
#define OUT_Y 3

// ---------------- tf32 helpers ----------------
__device__ __forceinline__ unsigned f2tf32(float x) {
    unsigned r;
    asm volatile("cvt.rna.tf32.f32 %0, %1;" : "=r"(r) : "f"(x));
    return r;
}

__device__ __forceinline__ float ex2(float x) {
    float y;
    asm("ex2.approx.ftz.f32 %0, %1;" : "=f"(y) : "f"(x));
    return y;
}

__device__ __forceinline__ void mma16818(float* c, const unsigned* a, const unsigned* b) {
    asm volatile(
        "mma.sync.aligned.m16n8k8.row.col.f32.tf32.tf32.f32 "
        "{%0,%1,%2,%3}, {%4,%5,%6,%7}, {%8,%9}, {%0,%1,%2,%3};"
        : "+f"(c[0]), "+f"(c[1]), "+f"(c[2]), "+f"(c[3])
        : "r"(a[0]), "r"(a[1]), "r"(a[2]), "r"(a[3]), "r"(b[0]), "r"(b[1]));
}

// ---------------- tf32 tensor-core GEMM ----------------
// C[M=8192, N=1024] = A[M,K=1024] * W[K,N] + bias (+residual)
// Block 128x128, BK=16, 256 threads = 8 warps (2 x 4), warp tile 64x32.
#define SSTR 136

__global__ __launch_bounds__(256, 2)
void gemm_tc_kernel(const float* __restrict__ A_ext, int a_sel,
                    const float* __restrict__ W,
                    const float* __restrict__ bias,
                    const float* __restrict__ residual,
                    int out_sel, int out_mode)
{
    __shared__ unsigned As[16 * SSTR];
    __shared__ unsigned Bs[16 * SSTR];

    const float* A = a_sel ? g_O : A_ext;
    float* outp;
    switch (out_sel) {
        case OUT_Q: outp = g_Q; break;
        case OUT_K: outp = g_K; break;
        case OUT_V: outp = g_V; break;
        default:    outp = g_Y; break;
    }

    const int tid  = threadIdx.x;
    const int brow = blockIdx.y;
    const int bcol = blockIdx.x;
    const int wid  = tid >> 5;
    const int lane = tid & 31;
    const int wm   = wid & 1;
    const int wn   = wid >> 1;
    const int row4 = lane >> 2;
    const int col  = lane & 3;

    const int la_m  = tid >> 1;
    const int la_k  = (tid & 1) * 8;
    const int lb_k  = tid >> 4;
    const int lb_n  = (tid & 15) * 8;

    const float* Ab = A + (size_t)(brow * 128 + la_m) * Dv + la_k;
    const float* Wb = W + (size_t)lb_k * Dv + bcol * 128 + lb_n;

    float acc[4][4][4];
#pragma unroll
    for (int i = 0; i < 4; i++)
#pragma unroll
        for (int j = 0; j < 4; j++)
#pragma unroll
            for (int r = 0; r < 4; r++) acc[i][j][r] = 0.f;

    for (int k0 = 0; k0 < Dv; k0 += 16) {
        float4 av0 = *(const float4*)(Ab + k0);
        float4 av1 = *(const float4*)(Ab + k0 + 4);
        As[(la_k + 0) * SSTR + la_m] = f2tf32(av0.x);
        As[(la_k + 1) * SSTR + la_m] = f2tf32(av0.y);
        As[(la_k + 2) * SSTR + la_m] = f2tf32(av0.z);
        As[(la_k + 3) * SSTR + la_m] = f2tf32(av0.w);
        As[(la_k + 4) * SSTR + la_m] = f2tf32(av1.x);
        As[(la_k + 5) * SSTR + la_m] = f2tf32(av1.y);
        As[(la_k + 6) * SSTR + la_m] = f2tf32(av1.z);
        As[(la_k + 7) * SSTR + la_m] = f2tf32(av1.w);
        float4 bv0 = *(const float4*)(Wb + (size_t)k0 * Dv);
        float4 bv1 = *(const float4*)(Wb + (size_t)k0 * Dv + 4);
        Bs[lb_k * SSTR + lb_n + 0] = f2tf32(bv0.x);
        Bs[lb_k * SSTR + lb_n + 1] = f2tf32(bv0.y);
        Bs[lb_k * SSTR + lb_n + 2] = f2tf32(bv0.z);
        Bs[lb_k * SSTR + lb_n + 3] = f2tf32(bv0.w);
        Bs[lb_k * SSTR + lb_n + 4] = f2tf32(bv1.x);
        Bs[lb_k * SSTR + lb_n + 5] = f2tf32(bv1.y);
        Bs[lb_k * SSTR + lb_n + 6] = f2tf32(bv1.z);
        Bs[lb_k * SSTR + lb_n + 7] = f2tf32(bv1.w);
        __syncthreads();

#pragma unroll
        for (int ks = 0; ks < 16; ks += 8) {
            unsigned af[4][4], bf[4][2];
#pragma unroll
            for (int i = 0; i < 4; i++) {
                const int mb = wm * 64 + i * 16 + row4;
                af[i][0] = As[(ks + col) * SSTR + mb];
                af[i][1] = As[(ks + col) * SSTR + mb + 8];
                af[i][2] = As[(ks + col + 4) * SSTR + mb];
                af[i][3] = As[(ks + col + 4) * SSTR + mb + 8];
            }
#pragma unroll
            for (int j = 0; j < 4; j++) {
                const int nb = wn * 32 + j * 8 + row4;
                bf[j][0] = Bs[(ks + col) * SSTR + nb];
                bf[j][1] = Bs[(ks + col + 4) * SSTR + nb];
            }
#pragma unroll
            for (int i = 0; i < 4; i++)
#pragma unroll
                for (int j = 0; j < 4; j++)
                    mma16818(acc[i][j], af[i], bf[j]);
        }
        __syncthreads();
    }

#pragma unroll
    for (int i = 0; i < 4; i++) {
#pragma unroll
        for (int j = 0; j < 4; j++) {
            const int m_lo = brow * 128 + wm * 64 + i * 16 + row4;
            const int n0   = bcol * 128 + wn * 32 + j * 8 + col * 2;
#pragma unroll
            for (int half = 0; half < 2; half++) {
                const int m = m_lo + half * 8;
                float v0 = acc[i][j][half * 2 + 0] + bias[n0];
                float v1 = acc[i][j][half * 2 + 1] + bias[n0 + 1];
                if (residual) {
                    v0 += residual[(size_t)m * Dv + n0];
                    v1 += residual[(size_t)m * Dv + n0 + 1];
                }
                if (out_mode == 0) {
                    *(float2*)&outp[(size_t)m * Dv + n0] = make_float2(v0, v1);
                } else {
                    const int b = m >> 11, l = m & 2047;
                    const int h = n0 >> 6, hd = n0 & 63;
                    float* p = &outp[((((size_t)b * Hv + h) * Lv) + l) * HDv + hd];
                    p[0] = v0; p[1] = v1;
                }
            }
        }
    }
}

// ---------------- tensor-core flash attention (tf32) ----------------
// Br=128, Bc=64, 8 warps; warp w owns q rows [w*16, w*16+16).
// smem (tf32 bits): Qs[128][68], Ks[64][68] (row-major [row][d]),
//                   Vt[64 d][68 kv] (transposed), Ps[128][68].
// Stride 68 == 4 mod 32 -> fragment LDS lane addr = 4g+t -> conflict-free.
#define QSTR 68
#define FLASH_SMEM (384 * QSTR * 4)   // (128+64+64+128)*68*4 = 104448 B

__global__ __launch_bounds__(256, 2)
void flash_tc_kernel()
{
    extern __shared__ unsigned smu[];
    unsigned* Qs = smu;                  // [128][QSTR]
    unsigned* Ks = smu + 128 * QSTR;     // [64][QSTR]
    unsigned* Vt = smu + 192 * QSTR;     // [64 d][QSTR]
    unsigned* Ps = smu + 256 * QSTR;     // [128][QSTR]

    const int tid  = threadIdx.x;
    const int bh   = blockIdx.y;         // b*16 + h
    const int qb   = blockIdx.x;         // q tile of 128
    const int wid  = tid >> 5;
    const int lane = tid & 31;
    const int g    = lane >> 2;          // groupID (row within 8)
    const int t    = lane & 3;           // threadID in group
    const int qw   = wid * 16;           // warp's q-row base (local)

    const float* Qp = g_Q + ((size_t)bh * Lv + qb * 128) * HDv;
    const float* Kp = g_K + (size_t)bh * Lv * HDv;
    const float* Vp = g_V + (size_t)bh * Lv * HDv;

    const float qscale = 0.125f * 1.4426950408889634f;  // 1/sqrt(64) * log2(e)

    // load Q (scaled, tf32), row-major
    {
        const int r0 = tid >> 2;
        const int cb = (tid & 3) * 4;
#pragma unroll
        for (int p = 0; p < 2; p++) {
            const int r = r0 + p * 64;
#pragma unroll
            for (int u = 0; u < 4; u++) {
                const int c = cb + u * 16;
                float4 qv = *(const float4*)(Qp + r * HDv + c);
                uint4 o;
                o.x = f2tf32(qv.x * qscale); o.y = f2tf32(qv.y * qscale);
                o.z = f2tf32(qv.z * qscale); o.w = f2tf32(qv.w * qscale);
                *(uint4*)&Qs[r * QSTR + c] = o;
            }
        }
    }

    float m0 = -1e30f, m1 = -1e30f, l0 = 0.f, l1 = 0.f;
    float o[8][4];
#pragma unroll
    for (int j = 0; j < 8; j++)
#pragma unroll
        for (int r = 0; r < 4; r++) o[j][r] = 0.f;

    for (int kb = 0; kb < Lv / 64; kb++) {
        // load K row-major + V transposed (tf32)
        {
            const int r  = tid >> 2;
            const int cb = (tid & 3) * 4;
            const float* kg = Kp + (size_t)(kb * 64 + r) * HDv;
            const float* vg = Vp + (size_t)(kb * 64 + r) * HDv;
#pragma unroll
            for (int u = 0; u < 4; u++) {
                const int c = cb + u * 16;
                float4 kv = *(const float4*)(kg + c);
                uint4 ko;
                ko.x = f2tf32(kv.x); ko.y = f2tf32(kv.y);
                ko.z = f2tf32(kv.z); ko.w = f2tf32(kv.w);
                *(uint4*)&Ks[r * QSTR + c] = ko;
                float4 vv = *(const float4*)(vg + c);
                Vt[(c + 0) * QSTR + r] = f2tf32(vv.x);
                Vt[(c + 1) * QSTR + r] = f2tf32(vv.y);
                Vt[(c + 2) * QSTR + r] = f2tf32(vv.z);
                Vt[(c + 3) * QSTR + r] = f2tf32(vv.w);
            }
        }
        __syncthreads();

        // ---- S = Q K^T ----
        float s[8][4];
#pragma unroll
        for (int j = 0; j < 8; j++)
#pragma unroll
            for (int r = 0; r < 4; r++) s[j][r] = 0.f;

#pragma unroll
        for (int k0 = 0; k0 < 64; k0 += 8) {
            unsigned a[4];
            a[0] = Qs[(qw + g) * QSTR + k0 + t];
            a[1] = Qs[(qw + g + 8) * QSTR + k0 + t];
            a[2] = Qs[(qw + g) * QSTR + k0 + t + 4];
            a[3] = Qs[(qw + g + 8) * QSTR + k0 + t + 4];
#pragma unroll
            for (int j = 0; j < 8; j++) {
                unsigned b[2];
                b[0] = Ks[(j * 8 + g) * QSTR + k0 + t];
                b[1] = Ks[(j * 8 + g) * QSTR + k0 + t + 4];
                mma16818(s[j], a, b);
            }
        }

        // ---- online softmax (scores already in log2 domain) ----
        float rmax0 = -1e30f, rmax1 = -1e30f;
#pragma unroll
        for (int j = 0; j < 8; j++) {
            rmax0 = fmaxf(rmax0, fmaxf(s[j][0], s[j][1]));
            rmax1 = fmaxf(rmax1, fmaxf(s[j][2], s[j][3]));
        }
#pragma unroll
        for (int off = 1; off <= 2; off <<= 1) {
            rmax0 = fmaxf(rmax0, __shfl_xor_sync(0xffffffffu, rmax0, off));
            rmax1 = fmaxf(rmax1, __shfl_xor_sync(0xffffffffu, rmax1, off));
        }
        const float mn0 = fmaxf(m0, rmax0);
        const float mn1 = fmaxf(m1, rmax1);
        const float cr0 = ex2(m0 - mn0);
        const float cr1 = ex2(m1 - mn1);

        float rs0 = 0.f, rs1 = 0.f;
#pragma unroll
        for (int j = 0; j < 8; j++) {
            const float p00 = ex2(s[j][0] - mn0);
            const float p01 = ex2(s[j][1] - mn0);
            const float p10 = ex2(s[j][2] - mn1);
            const float p11 = ex2(s[j][3] - mn1);
            rs0 += p00 + p01;
            rs1 += p10 + p11;
            uint2 w0, w1;
            w0.x = f2tf32(p00); w0.y = f2tf32(p01);
            w1.x = f2tf32(p10); w1.y = f2tf32(p11);
            *(uint2*)&Ps[(qw + g) * QSTR + j * 8 + 2 * t]     = w0;
            *(uint2*)&Ps[(qw + g + 8) * QSTR + j * 8 + 2 * t] = w1;
        }
#pragma unroll
        for (int off = 1; off <= 2; off <<= 1) {
            rs0 += __shfl_xor_sync(0xffffffffu, rs0, off);
            rs1 += __shfl_xor_sync(0xffffffffu, rs1, off);
        }
        l0 = l0 * cr0 + rs0;
        l1 = l1 * cr1 + rs1;
        m0 = mn0; m1 = mn1;
#pragma unroll
        for (int j = 0; j < 8; j++) {
            o[j][0] *= cr0; o[j][1] *= cr0;
            o[j][2] *= cr1; o[j][3] *= cr1;
        }
        __syncwarp();

        // ---- O += P V ----
#pragma unroll
        for (int k0 = 0; k0 < 64; k0 += 8) {
            unsigned a[4];
            a[0] = Ps[(qw + g) * QSTR + k0 + t];
            a[1] = Ps[(qw + g + 8) * QSTR + k0 + t];
            a[2] = Ps[(qw + g) * QSTR + k0 + t + 4];
            a[3] = Ps[(qw + g + 8) * QSTR + k0 + t + 4];
#pragma unroll
            for (int j = 0; j < 8; j++) {
                unsigned b[2];
                b[0] = Vt[(j * 8 + g) * QSTR + k0 + t];
                b[1] = Vt[(j * 8 + g) * QSTR + k0 + t + 4];
                mma16818(o[j], a, b);
            }
        }
        __syncthreads();
    }

    // ---- write O / l to g_O [B,L,D] ----
    const int b = bh >> 4, h = bh & 15;
    const float inv0 = 1.f / l0;
    const float inv1 = 1.f / l1;
    const int q0 = qb * 128 + qw + g;
    const int q1 = q0 + 8;
#pragma unroll
    for (int j = 0; j < 8; j++) {
        const int colD = h * HDv + j * 8 + 2 * t;
        *(float2*)&g_O[((size_t)b * Lv + q0) * Dv + colD] =
            make_float2(o[j][0] * inv0, o[j][1] * inv0);
        *(float2*)&g_O[((size_t)b * Lv + q1) * Dv + colD] =
            make_float2(o[j][2] * inv1, o[j][3] * inv1);
    }
}

// ---------------- LayerNorm: one block per row ----------------
__device__ __forceinline__ float blockReduceSum(float val)
{
    __shared__ float sh[8];
    const int lane = threadIdx.x & 31;
    const int wid  = threadIdx.x >> 5;
#pragma unroll
    for (int o = 16; o > 0; o >>= 1) val += __shfl_xor_sync(0xffffffffu, val, o);
    __syncthreads();
    if (lane == 0) sh[wid] = val;
    __syncthreads();
    if (wid == 0) {
        val = (lane < 8) ? sh[lane] : 0.f;
#pragma unroll
        for (int o = 4; o > 0; o >>= 1) val += __shfl_xor_sync(0xffffffffu, val, o);
        if (lane == 0) sh[0] = val;
    }
    __syncthreads();
    return sh[0];
}

__global__ __launch_bounds__(256)
void layernorm_kernel(const float* __restrict__ gamma,
                      const float* __restrict__ beta,
                      float* __restrict__ out)
{
    const int row = blockIdx.x;
    const int tid = threadIdx.x;
    const float* y = g_Y + (size_t)row * Dv;

    float v[4];
#pragma unroll
    for (int i = 0; i < 4; i++) v[i] = y[tid + i * 256];

    const float total = blockReduceSum(v[0] + v[1] + v[2] + v[3]);
    const float mu = total * (1.f / Dv);

    float d2 = 0.f;
#pragma unroll
    for (int i = 0; i < 4; i++) {
        const float d = v[i] - mu;
        d2 += d * d;
    }
    const float var = blockReduceSum(d2) * (1.f / Dv);
    const float rs = rsqrtf(var + EPSv);

#pragma unroll
    for (int i = 0; i < 4; i++) {
        const int c = tid + i * 256;
        out[(size_t)row * Dv + c] = (v[i] - mu) * rs * gamma[c] + beta[c];
    }
}

// ---------------- launch ----------------
extern "C" void kernel_launch(void* const* d_in, const int* in_sizes, int n_in,
                              void* d_out, int out_size)
{
    (void)in_sizes; (void)n_in; (void)out_size;
    const float* x     = (const float*)d_in[0];
    const float* Wq    = (const float*)d_in[1];
    const float* bq    = (const float*)d_in[2];
    const float* Wk    = (const float*)d_in[3];
    const float* bk    = (const float*)d_in[4];
    const float* Wv    = (const float*)d_in[5];
    const float* bv    = (const float*)d_in[6];
    const float* Wo    = (const float*)d_in[7];
    const float* bo    = (const float*)d_in[8];
    const float* gamma = (const float*)d_in[9];
    const float* beta  = (const float*)d_in[10];
    float* out = (float*)d_out;

    cudaFuncSetAttribute(flash_tc_kernel,
                         cudaFuncAttributeMaxDynamicSharedMemorySize, FLASH_SMEM);

    dim3 gg(Dv / 128, Mv / 128);   // (8, 64)
    gemm_tc_kernel<<<gg, 256>>>(x, 0, Wq, bq, nullptr, OUT_Q, 1);
    gemm_tc_kernel<<<gg, 256>>>(x, 0, Wk, bk, nullptr, OUT_K, 1);
    gemm_tc_kernel<<<gg, 256>>>(x, 0, Wv, bv, nullptr, OUT_V, 1);

    flash_tc_kernel<<<dim3(Lv / 128, Bv * Hv), 256, FLASH_SMEM>>>();

    gemm_tc_kernel<<<gg, 256>>>(nullptr, 1, Wo, bo, x, OUT_Y, 0);

    layernorm_kernel<<<Mv, 256>>>(gamma, beta, out);
}

// round 5
// speedup vs baseline: 5.5920x; 1.4503x over previous
#include <cuda_runtime.h>
#include <cuda_bf16.h>
#include <math.h>

// Problem constants
#define Bv 4
#define Lv 2048
#define Dv 1024
#define Hv 16
#define HDv 64
#define Mv (Bv * Lv)          // 8192 rows
#define EPSv 1e-5f

// ---------------- scratch (device globals; no allocs allowed) ----------------
__device__ float g_Q[Bv * Hv * Lv * HDv];  // [B,H,L,HD]
__device__ float g_K[Bv * Hv * Lv * HDv];
__device__ float g_V[Bv * Hv * Lv * HDv];
__device__ float g_O[Mv * Dv];             // attention out, [B,L,D]
__device__ float g_Y[Mv * Dv];             // pre-LN residual sum

#define OUT_Q 0
#define OUT_K 1
#define OUT_V 2
#define OUT_Y 3

// ---------------- helpers ----------------
__device__ __forceinline__ unsigned f2tf32(float x) {
    unsigned r;
    asm volatile("cvt.rna.tf32.f32 %0, %1;" : "=r"(r) : "f"(x));
    return r;
}

__device__ __forceinline__ float ex2(float x) {
    float y;
    asm("ex2.approx.ftz.f32 %0, %1;" : "=f"(y) : "f"(x));
    return y;
}

__device__ __forceinline__ unsigned smem_u32(const void* p) {
    return (unsigned)__cvta_generic_to_shared(p);
}

__device__ __forceinline__ void cp_async16(unsigned dst, const float* src) {
    asm volatile("cp.async.cg.shared.global [%0], [%1], 16;" :: "r"(dst), "l"(src));
}
__device__ __forceinline__ void cp_commit() {
    asm volatile("cp.async.commit_group;");
}
template<int N> __device__ __forceinline__ void cp_wait() {
    asm volatile("cp.async.wait_group %0;" :: "n"(N));
}

__device__ __forceinline__ void mma16818(float* c, const unsigned* a, const unsigned* b) {
    asm volatile(
        "mma.sync.aligned.m16n8k8.row.col.f32.tf32.tf32.f32 "
        "{%0,%1,%2,%3}, {%4,%5,%6,%7}, {%8,%9}, {%0,%1,%2,%3};"
        : "+f"(c[0]), "+f"(c[1]), "+f"(c[2]), "+f"(c[3])
        : "r"(a[0]), "r"(a[1]), "r"(a[2]), "r"(a[3]), "r"(b[0]), "r"(b[1]));
}

__device__ __forceinline__ void mma_bf16(float* c, unsigned a0, unsigned a1, unsigned a2, unsigned a3,
                                         unsigned b0, unsigned b1) {
    asm volatile(
        "mma.sync.aligned.m16n8k16.row.col.f32.bf16.bf16.f32 "
        "{%0,%1,%2,%3}, {%4,%5,%6,%7}, {%8,%9}, {%0,%1,%2,%3};"
        : "+f"(c[0]), "+f"(c[1]), "+f"(c[2]), "+f"(c[3])
        : "r"(a0), "r"(a1), "r"(a2), "r"(a3), "r"(b0), "r"(b1));
}

__device__ __forceinline__ void ldsm4(unsigned& r0, unsigned& r1, unsigned& r2, unsigned& r3, unsigned addr) {
    asm volatile("ldmatrix.sync.aligned.m8n8.x4.shared.b16 {%0,%1,%2,%3}, [%4];"
                 : "=r"(r0), "=r"(r1), "=r"(r2), "=r"(r3) : "r"(addr));
}
__device__ __forceinline__ void ldsm4t(unsigned& r0, unsigned& r1, unsigned& r2, unsigned& r3, unsigned addr) {
    asm volatile("ldmatrix.sync.aligned.m8n8.x4.trans.shared.b16 {%0,%1,%2,%3}, [%4];"
                 : "=r"(r0), "=r"(r1), "=r"(r2), "=r"(r3) : "r"(addr));
}

// ---------------- tf32 tensor-core GEMM, 4-stage cp.async pipeline ----------------
// C[M=8192, N=1024] = A[M,K=1024] * W[K,N] + bias (+residual)
// Block 128x128, BK=16/stage, 256 threads = 8 warps (2 x 4), warp tile 64x32.
#define GSTAGES 4
#define ASTR 20                     // 16 + 4 pad (floats)
#define BSTR 136                    // 128 + 8 (floats)
#define A_STAGE (128 * ASTR)        // 2560 floats
#define B_STAGE (16 * BSTR)         // 2176 floats
#define GEMM_SMEM (GSTAGES * (A_STAGE + B_STAGE) * 4)   // 75776 B

__global__ __launch_bounds__(256, 2)
void gemm_tc_kernel(const float* __restrict__ A_ext, int a_sel,
                    const float* __restrict__ W,
                    const float* __restrict__ bias,
                    const float* __restrict__ residual,
                    int out_sel, int out_mode)
{
    extern __shared__ float gsm[];
    float* sA = gsm;                       // [GSTAGES][A_STAGE]
    float* sB = gsm + GSTAGES * A_STAGE;   // [GSTAGES][B_STAGE]

    const float* A = a_sel ? g_O : A_ext;
    float* outp;
    switch (out_sel) {
        case OUT_Q: outp = g_Q; break;
        case OUT_K: outp = g_K; break;
        case OUT_V: outp = g_V; break;
        default:    outp = g_Y; break;
    }

    const int tid  = threadIdx.x;
    const int brow = blockIdx.y;
    const int bcol = blockIdx.x;
    const int wid  = tid >> 5;
    const int lane = tid & 31;
    const int wm   = wid & 1;
    const int wn   = wid >> 1;
    const int row4 = lane >> 2;    // g
    const int col  = lane & 3;     // t

    // copy mapping: A 512 chunks (row=c>>2, kc=(c&3)*4), B 512 chunks (row=c>>5, nc=(c&31)*4)
    const int ac0_row = tid >> 2,          ac0_kc = (tid & 3) * 4;
    const int ac1_row = (tid + 256) >> 2,  ac1_kc = (tid & 3) * 4;
    const int bc0_row = tid >> 5,          bc0_nc = (tid & 31) * 4;
    const int bc1_row = (tid + 256) >> 5,  bc1_nc = (tid & 31) * 4;

    const float* Agb = A + (size_t)(brow * 128) * Dv;
    const float* Wgb = W + bcol * 128;

    float acc[4][4][4];
#pragma unroll
    for (int i = 0; i < 4; i++)
#pragma unroll
        for (int j = 0; j < 4; j++)
#pragma unroll
            for (int r = 0; r < 4; r++) acc[i][j][r] = 0.f;

    // stage copy
    auto copy_stage = [&](int s, int k0) {
        float* as = sA + s * A_STAGE;
        float* bs = sB + s * B_STAGE;
        cp_async16(smem_u32(as + ac0_row * ASTR + ac0_kc),
                   Agb + (size_t)ac0_row * Dv + k0 + ac0_kc);
        cp_async16(smem_u32(as + ac1_row * ASTR + ac1_kc),
                   Agb + (size_t)ac1_row * Dv + k0 + ac1_kc);
        cp_async16(smem_u32(bs + bc0_row * BSTR + bc0_nc),
                   Wgb + (size_t)(k0 + bc0_row) * Dv + bc0_nc);
        cp_async16(smem_u32(bs + bc1_row * BSTR + bc1_nc),
                   Wgb + (size_t)(k0 + bc1_row) * Dv + bc1_nc);
    };

    const int NK = Dv / 16;   // 64 stages of work
#pragma unroll
    for (int s = 0; s < GSTAGES - 1; s++) {
        copy_stage(s, s * 16);
        cp_commit();
    }

    for (int kt = 0; kt < NK; kt++) {
        cp_wait<GSTAGES - 2>();
        __syncthreads();

        // issue next copy before compute
        const int nxt = kt + GSTAGES - 1;
        if (nxt < NK) copy_stage(nxt & (GSTAGES - 1), nxt * 16);
        cp_commit();

        const float* as = sA + (kt & (GSTAGES - 1)) * A_STAGE;
        const float* bs = sB + (kt & (GSTAGES - 1)) * B_STAGE;

#pragma unroll
        for (int ks = 0; ks < 16; ks += 8) {
            unsigned af[4][4], bf[4][2];
#pragma unroll
            for (int i = 0; i < 4; i++) {
                const int mb = wm * 64 + i * 16 + row4;
                af[i][0] = f2tf32(as[mb * ASTR + ks + col]);
                af[i][1] = f2tf32(as[(mb + 8) * ASTR + ks + col]);
                af[i][2] = f2tf32(as[mb * ASTR + ks + col + 4]);
                af[i][3] = f2tf32(as[(mb + 8) * ASTR + ks + col + 4]);
            }
#pragma unroll
            for (int j = 0; j < 4; j++) {
                const int nb = wn * 32 + j * 8 + row4;
                bf[j][0] = f2tf32(bs[(ks + col) * BSTR + nb]);
                bf[j][1] = f2tf32(bs[(ks + col + 4) * BSTR + nb]);
            }
#pragma unroll
            for (int i = 0; i < 4; i++)
#pragma unroll
                for (int j = 0; j < 4; j++)
                    mma16818(acc[i][j], af[i], bf[j]);
        }
        __syncthreads();
    }

    // epilogue
#pragma unroll
    for (int i = 0; i < 4; i++) {
#pragma unroll
        for (int j = 0; j < 4; j++) {
            const int m_lo = brow * 128 + wm * 64 + i * 16 + row4;
            const int n0   = bcol * 128 + wn * 32 + j * 8 + col * 2;
#pragma unroll
            for (int half = 0; half < 2; half++) {
                const int m = m_lo + half * 8;
                float v0 = acc[i][j][half * 2 + 0] + bias[n0];
                float v1 = acc[i][j][half * 2 + 1] + bias[n0 + 1];
                if (residual) {
                    v0 += residual[(size_t)m * Dv + n0];
                    v1 += residual[(size_t)m * Dv + n0 + 1];
                }
                if (out_mode == 0) {
                    *(float2*)&outp[(size_t)m * Dv + n0] = make_float2(v0, v1);
                } else {
                    const int b = m >> 11, l = m & 2047;
                    const int h = n0 >> 6, hd = n0 & 63;
                    float* p = &outp[((((size_t)b * Hv + h) * Lv) + l) * HDv + hd];
                    p[0] = v0; p[1] = v1;
                }
            }
        }
    }
}

// ---------------- bf16 tensor-core flash attention + ldmatrix ----------------
// Br=128, Bc=64, 8 warps; warp w owns q rows [w*16, w*16+16).
// smem bf16, stride 72 (144B rows -> conflict-free LDSM footprints):
//   Qs[128][72], Ks[64][72], Vs[64][72] (all row-major [row][d]), Ps[128][72].
#define FQSTR 72
#define FQ_OFF 0
#define FK_OFF (128 * FQSTR)              // 9216
#define FV_OFF (FK_OFF + 64 * FQSTR)      // 13824
#define FP_OFF (FV_OFF + 64 * FQSTR)      // 18432
#define FLASH_SMEM ((FP_OFF + 128 * FQSTR) * 2)   // 55296 B

__global__ __launch_bounds__(256, 2)
void flash_tc_kernel()
{
    extern __shared__ __nv_bfloat16 fsm[];
    const unsigned sbase = smem_u32(fsm);

    const int tid  = threadIdx.x;
    const int bh   = blockIdx.y;         // b*16 + h
    const int qb   = blockIdx.x;         // q tile of 128
    const int wid  = tid >> 5;
    const int lane = tid & 31;
    const int g    = lane >> 2;          // groupID
    const int t    = lane & 3;           // thread in group
    const int qw   = wid * 16;           // warp's q-row base (local)

    const float* Qp = g_Q + ((size_t)bh * Lv + qb * 128) * HDv;
    const float* Kp = g_K + (size_t)bh * Lv * HDv;
    const float* Vp = g_V + (size_t)bh * Lv * HDv;

    const float qscale = 0.125f * 1.4426950408889634f;  // 1/sqrt(64) * log2(e)

    // tile-load mapping
    const int lr = tid >> 2;            // 0..63
    const int cb = (tid & 3) * 4;       // 0,4,8,12

    // load Q (scaled, bf16) rows 0..127
#pragma unroll
    for (int p = 0; p < 2; p++) {
        const int r = lr + p * 64;
#pragma unroll
        for (int u = 0; u < 4; u++) {
            const int c = cb + u * 16;
            float4 qv = *(const float4*)(Qp + r * HDv + c);
            __nv_bfloat162 lo = __float22bfloat162_rn(make_float2(qv.x * qscale, qv.y * qscale));
            __nv_bfloat162 hi = __float22bfloat162_rn(make_float2(qv.z * qscale, qv.w * qscale));
            *(__nv_bfloat162*)&fsm[FQ_OFF + r * FQSTR + c]     = lo;
            *(__nv_bfloat162*)&fsm[FQ_OFF + r * FQSTR + c + 2] = hi;
        }
    }

    // ldmatrix lane address bases (bytes)
    const int a_row = lane & 15;
    const int a_k8  = (lane >> 4) << 3;
    const unsigned qA = sbase + (unsigned)(FQ_OFF + (qw + a_row) * FQSTR + a_k8) * 2;
    const unsigned pA = sbase + (unsigned)(FP_OFF + (qw + a_row) * FQSTR + a_k8) * 2;

    const int b_row = ((lane >> 4) << 3) + (lane & 7);
    const int b_k8  = ((lane >> 3) & 1) << 3;
    const unsigned kB = sbase + (unsigned)(FK_OFF + b_row * FQSTR + b_k8) * 2;

    const int v_row = (((lane >> 3) & 1) << 3) + (lane & 7);
    const int v_col = (lane >> 4) << 3;
    const unsigned vB = sbase + (unsigned)(FV_OFF + v_row * FQSTR + v_col) * 2;

    float m0 = -1e30f, m1 = -1e30f, l0 = 0.f, l1 = 0.f;
    float o[8][4];
#pragma unroll
    for (int j = 0; j < 8; j++)
#pragma unroll
        for (int r = 0; r < 4; r++) o[j][r] = 0.f;

    for (int kb = 0; kb < Lv / 64; kb++) {
        // load K, V tiles (row-major bf16)
        {
            const float* kg = Kp + (size_t)(kb * 64 + lr) * HDv;
            const float* vg = Vp + (size_t)(kb * 64 + lr) * HDv;
#pragma unroll
            for (int u = 0; u < 4; u++) {
                const int c = cb + u * 16;
                float4 kv = *(const float4*)(kg + c);
                *(__nv_bfloat162*)&fsm[FK_OFF + lr * FQSTR + c]     = __float22bfloat162_rn(make_float2(kv.x, kv.y));
                *(__nv_bfloat162*)&fsm[FK_OFF + lr * FQSTR + c + 2] = __float22bfloat162_rn(make_float2(kv.z, kv.w));
                float4 vv = *(const float4*)(vg + c);
                *(__nv_bfloat162*)&fsm[FV_OFF + lr * FQSTR + c]     = __float22bfloat162_rn(make_float2(vv.x, vv.y));
                *(__nv_bfloat162*)&fsm[FV_OFF + lr * FQSTR + c + 2] = __float22bfloat162_rn(make_float2(vv.z, vv.w));
            }
        }
        __syncthreads();

        // ---- S = Q K^T ----
        float s[8][4];
#pragma unroll
        for (int j = 0; j < 8; j++)
#pragma unroll
            for (int r = 0; r < 4; r++) s[j][r] = 0.f;

#pragma unroll
        for (int k0 = 0; k0 < 64; k0 += 16) {
            unsigned a0, a1, a2, a3;
            ldsm4(a0, a1, a2, a3, qA + k0 * 2);
#pragma unroll
            for (int jp = 0; jp < 4; jp++) {
                unsigned b0, b1, b2, b3;
                ldsm4(b0, b1, b2, b3, kB + (unsigned)(jp * 16 * FQSTR + k0) * 2);
                mma_bf16(s[2 * jp],     a0, a1, a2, a3, b0, b1);
                mma_bf16(s[2 * jp + 1], a0, a1, a2, a3, b2, b3);
            }
        }

        // ---- online softmax (scores in log2 domain) ----
        float rmax0 = -1e30f, rmax1 = -1e30f;
#pragma unroll
        for (int j = 0; j < 8; j++) {
            rmax0 = fmaxf(rmax0, fmaxf(s[j][0], s[j][1]));
            rmax1 = fmaxf(rmax1, fmaxf(s[j][2], s[j][3]));
        }
#pragma unroll
        for (int off = 1; off <= 2; off <<= 1) {
            rmax0 = fmaxf(rmax0, __shfl_xor_sync(0xffffffffu, rmax0, off));
            rmax1 = fmaxf(rmax1, __shfl_xor_sync(0xffffffffu, rmax1, off));
        }
        const float mn0 = fmaxf(m0, rmax0);
        const float mn1 = fmaxf(m1, rmax1);
        const float cr0 = ex2(m0 - mn0);
        const float cr1 = ex2(m1 - mn1);

        float rs0 = 0.f, rs1 = 0.f;
#pragma unroll
        for (int j = 0; j < 8; j++) {
            const float p00 = ex2(s[j][0] - mn0);
            const float p01 = ex2(s[j][1] - mn0);
            const float p10 = ex2(s[j][2] - mn1);
            const float p11 = ex2(s[j][3] - mn1);
            rs0 += p00 + p01;
            rs1 += p10 + p11;
            *(__nv_bfloat162*)&fsm[FP_OFF + (qw + g) * FQSTR + j * 8 + 2 * t] =
                __float22bfloat162_rn(make_float2(p00, p01));
            *(__nv_bfloat162*)&fsm[FP_OFF + (qw + g + 8) * FQSTR + j * 8 + 2 * t] =
                __float22bfloat162_rn(make_float2(p10, p11));
        }
#pragma unroll
        for (int off = 1; off <= 2; off <<= 1) {
            rs0 += __shfl_xor_sync(0xffffffffu, rs0, off);
            rs1 += __shfl_xor_sync(0xffffffffu, rs1, off);
        }
        l0 = l0 * cr0 + rs0;
        l1 = l1 * cr1 + rs1;
        m0 = mn0; m1 = mn1;
#pragma unroll
        for (int j = 0; j < 8; j++) {
            o[j][0] *= cr0; o[j][1] *= cr0;
            o[j][2] *= cr1; o[j][3] *= cr1;
        }
        __syncwarp();

        // ---- O += P V  (V via ldmatrix.trans) ----
#pragma unroll
        for (int k0 = 0; k0 < 64; k0 += 16) {
            unsigned a0, a1, a2, a3;
            ldsm4(a0, a1, a2, a3, pA + k0 * 2);
#pragma unroll
            for (int jp = 0; jp < 4; jp++) {
                unsigned b0, b1, b2, b3;
                ldsm4t(b0, b1, b2, b3, vB + (unsigned)(k0 * FQSTR + jp * 16) * 2);
                mma_bf16(o[2 * jp],     a0, a1, a2, a3, b0, b1);
                mma_bf16(o[2 * jp + 1], a0, a1, a2, a3, b2, b3);
            }
        }
        __syncthreads();
    }

    // ---- write O to g_O [B,L,D] ----
    const int b = bh >> 4, h = bh & 15;
    const float inv0 = 1.f / l0;
    const float inv1 = 1.f / l1;
    const int q0 = qb * 128 + qw + g;
    const int q1 = q0 + 8;
#pragma unroll
    for (int j = 0; j < 8; j++) {
        const int colD = h * HDv + j * 8 + 2 * t;
        *(float2*)&g_O[((size_t)b * Lv + q0) * Dv + colD] =
            make_float2(o[j][0] * inv0, o[j][1] * inv0);
        *(float2*)&g_O[((size_t)b * Lv + q1) * Dv + colD] =
            make_float2(o[j][2] * inv1, o[j][3] * inv1);
    }
}

// ---------------- LayerNorm: one block per row ----------------
__device__ __forceinline__ float blockReduceSum(float val)
{
    __shared__ float sh[8];
    const int lane = threadIdx.x & 31;
    const int wid  = threadIdx.x >> 5;
#pragma unroll
    for (int o = 16; o > 0; o >>= 1) val += __shfl_xor_sync(0xffffffffu, val, o);
    __syncthreads();
    if (lane == 0) sh[wid] = val;
    __syncthreads();
    if (wid == 0) {
        val = (lane < 8) ? sh[lane] : 0.f;
#pragma unroll
        for (int o = 4; o > 0; o >>= 1) val += __shfl_xor_sync(0xffffffffu, val, o);
        if (lane == 0) sh[0] = val;
    }
    __syncthreads();
    return sh[0];
}

__global__ __launch_bounds__(256)
void layernorm_kernel(const float* __restrict__ gamma,
                      const float* __restrict__ beta,
                      float* __restrict__ out)
{
    const int row = blockIdx.x;
    const int tid = threadIdx.x;
    const float* y = g_Y + (size_t)row * Dv;

    float v[4];
#pragma unroll
    for (int i = 0; i < 4; i++) v[i] = y[tid + i * 256];

    const float total = blockReduceSum(v[0] + v[1] + v[2] + v[3]);
    const float mu = total * (1.f / Dv);

    float d2 = 0.f;
#pragma unroll
    for (int i = 0; i < 4; i++) {
        const float d = v[i] - mu;
        d2 += d * d;
    }
    const float var = blockReduceSum(d2) * (1.f / Dv);
    const float rs = rsqrtf(var + EPSv);

#pragma unroll
    for (int i = 0; i < 4; i++) {
        const int c = tid + i * 256;
        out[(size_t)row * Dv + c] = (v[i] - mu) * rs * gamma[c] + beta[c];
    }
}

// ---------------- launch ----------------
extern "C" void kernel_launch(void* const* d_in, const int* in_sizes, int n_in,
                              void* d_out, int out_size)
{
    (void)in_sizes; (void)n_in; (void)out_size;
    const float* x     = (const float*)d_in[0];
    const float* Wq    = (const float*)d_in[1];
    const float* bq    = (const float*)d_in[2];
    const float* Wk    = (const float*)d_in[3];
    const float* bk    = (const float*)d_in[4];
    const float* Wv    = (const float*)d_in[5];
    const float* bv    = (const float*)d_in[6];
    const float* Wo    = (const float*)d_in[7];
    const float* bo    = (const float*)d_in[8];
    const float* gamma = (const float*)d_in[9];
    const float* beta  = (const float*)d_in[10];
    float* out = (float*)d_out;

    cudaFuncSetAttribute(flash_tc_kernel,
                         cudaFuncAttributeMaxDynamicSharedMemorySize, FLASH_SMEM);
    cudaFuncSetAttribute(gemm_tc_kernel,
                         cudaFuncAttributeMaxDynamicSharedMemorySize, GEMM_SMEM);

    dim3 gg(Dv / 128, Mv / 128);   // (8, 64)
    gemm_tc_kernel<<<gg, 256, GEMM_SMEM>>>(x, 0, Wq, bq, nullptr, OUT_Q, 1);
    gemm_tc_kernel<<<gg, 256, GEMM_SMEM>>>(x, 0, Wk, bk, nullptr, OUT_K, 1);
    gemm_tc_kernel<<<gg, 256, GEMM_SMEM>>>(x, 0, Wv, bv, nullptr, OUT_V, 1);

    flash_tc_kernel<<<dim3(Lv / 128, Bv * Hv), 256, FLASH_SMEM>>>();

    gemm_tc_kernel<<<gg, 256, GEMM_SMEM>>>(nullptr, 1, Wo, bo, x, OUT_Y, 0);

    layernorm_kernel<<<Mv, 256>>>(gamma, beta, out);
}